// round 10
// baseline (speedup 1.0000x reference)
#include <cuda_runtime.h>

// Fused local NCC loss (kernel=3, zero 'same' padding) over 192^3 f32 volumes.
// One warp spans d=192: lane owns d={2l, 64+2l, 128+2l} as f32x2 packs
// (coalesced LDG.64). H=1 row per warp; rows h-1,h,h+1 via per-row pointers
// (zero-buffer redirect at h edges). w marched with a compact T-scheme:
// T[s] = plane(w-1)+plane(w), B[s] = plane(w); new plane consumed per pack
// immediately (60 regs of ring state). d-seam via publish-SEL + index-shfl,
// packed f32x2 seam + NCC epilogue. __launch_bounds__(64,10) for 20 warps/SM.

#define SZ    192
#define SZ2   (SZ * SZ)
#define NTOT  (SZ * SZ * SZ)
#define WCHUNK 12
#define GY     96              // 192 h rows / 2 warps per block
#define GZ     16              // 192 / WCHUNK
#define NBLK   (GY * GZ)       // 1536 (fills 10 blocks/SM in ~one wave)

typedef unsigned long long u64;

__device__ float        g_zero[4608];          // static zero (BSS) pad source
__device__ float        g_partial[NBLK];
__device__ unsigned int g_count = 0;

__device__ __forceinline__ u64 pk2(float lo, float hi) {
    u64 r; asm("mov.b64 %0, {%1, %2};" : "=l"(r) : "f"(lo), "f"(hi)); return r;
}
__device__ __forceinline__ void upk2(u64 v, float& lo, float& hi) {
    asm("mov.b64 {%0, %1}, %2;" : "=f"(lo), "=f"(hi) : "l"(v));
}
__device__ __forceinline__ u64 add2(u64 a, u64 b) {
    u64 r; asm("add.rn.f32x2 %0, %1, %2;" : "=l"(r) : "l"(a), "l"(b)); return r;
}
__device__ __forceinline__ u64 mul2(u64 a, u64 b) {
    u64 r; asm("mul.rn.f32x2 %0, %1, %2;" : "=l"(r) : "l"(a), "l"(b)); return r;
}
__device__ __forceinline__ u64 fma2(u64 a, u64 b, u64 c) {
    u64 r; asm("fma.rn.f32x2 %0, %1, %2, %3;" : "=l"(r) : "l"(a), "l"(b), "l"(c)); return r;
}

// h-summed plane components {I,J,II,JJ,IJ} from 6 raw f32x2 values.
__device__ __forceinline__ void build5(u64 (&c)[5],
    u64 I0, u64 I1, u64 I2, u64 J0, u64 J1, u64 J2)
{
    c[0] = add2(add2(I0, I1), I2);
    c[1] = add2(add2(J0, J1), J2);
    u64 a = mul2(I0, I0); a = fma2(I1, I1, a); a = fma2(I2, I2, a); c[2] = a;
    a = mul2(J0, J0); a = fma2(J1, J1, a); a = fma2(J2, J2, a); c[3] = a;
    a = mul2(I0, J0); a = fma2(I1, J1, a); a = fma2(I2, J2, a); c[4] = a;
}

#define LOADRAWS(OFF, COND)                                                   \
    u64 I0 = 0, I1 = 0, I2 = 0, J0 = 0, J1 = 0, J2 = 0;                       \
    if (COND) {                                                               \
        I0 = *(const u64*)(pI[0] + (OFF)); J0 = *(const u64*)(pJ[0] + (OFF)); \
        I1 = *(const u64*)(pI[1] + (OFF)); J1 = *(const u64*)(pJ[1] + (OFF)); \
        I2 = *(const u64*)(pI[2] + (OFF)); J2 = *(const u64*)(pJ[2] + (OFF)); \
    }

__global__ __launch_bounds__(64, 10)
void lncc_fused_kernel(const float* __restrict__ pred,
                       const float* __restrict__ targ,
                       float* __restrict__ out)
{
    const int lane = threadIdx.x;                  // 0..31
    const int h    = blockIdx.y * 2 + threadIdx.y; // one h row per warp
    const int w0   = blockIdx.z * WCHUNK;

    const u64 ninv2 = pk2(-1.0f / 27.0f, -1.0f / 27.0f);
    const u64 eps2  = pk2(1e-5f, 1e-5f);

    // Per-row pointers (positioned at plane w0-1); h-edge rows -> zero buffer.
    const float* pI[3];
    const float* pJ[3];
    #pragma unroll
    for (int r = 0; r < 3; r++) {
        int hh = h - 1 + r;
        bool ok = (hh >= 0) && (hh < SZ);
        long off = (long)hh * SZ2 + (long)(w0 - 1) * SZ + 2 * lane;
        pI[r] = ok ? pred + off : g_zero + 2 * lane;
        pJ[r] = ok ? targ + off : g_zero + 2 * lane;
    }

    u64 T[3][5], Bv[3][5];
    {   // prologue: T = plane(w0-1)+plane(w0), B = plane(w0)
        const bool okm = (w0 >= 1);
        #pragma unroll
        for (int s = 0; s < 3; s++) {
            u64 c0[5], c1[5];
            {
                LOADRAWS(64 * s, okm)
                build5(c0, I0, I1, I2, J0, J1, J2);
            }
            {
                LOADRAWS(SZ + 64 * s, true)
                build5(c1, I0, I1, I2, J0, J1, J2);
            }
            #pragma unroll
            for (int c = 0; c < 5; c++) {
                T[s][c]  = add2(c0[c], c1[c]);
                Bv[s][c] = c1[c];
            }
        }
    }
    #pragma unroll
    for (int r = 0; r < 3; r++) { pI[r] += 2 * SZ; pJ[r] += 2 * SZ; }

    float acc = 0.f;
    // outputs w = w0 .. w0+WCHUNK-1 ; step t consumes plane w0+1+t.
    #pragma unroll 1
    for (int t = 0; t < WCHUNK; t++) {
        const bool ld = (w0 + 1 + t) < SZ;
        float wlo[5][3], whi[5][3];
        #pragma unroll
        for (int s = 0; s < 3; s++) {
            LOADRAWS(64 * s, ld)
            u64 cc[5];
            build5(cc, I0, I1, I2, J0, J1, J2);
            #pragma unroll
            for (int c = 0; c < 5; c++) {
                u64 W = add2(T[s][c], cc[c]);
                upk2(W, wlo[c][s], whi[c][s]);
                T[s][c]  = add2(Bv[s][c], cc[c]);
                Bv[s][c] = cc[c];
            }
        }
        // d-seam + packed NCC (round-6 form)
        u64 o[5][3];
        #pragma unroll
        for (int c = 0; c < 5; c++) {
            #pragma unroll
            for (int s = 0; s < 3; s++) {
                // prev = elem(d0-1): lane l-1's hi[s]; lane0 <- lane31's hi[s-1] (0 if s==0)
                float pubp = (lane == 31) ? (s ? whi[c][s - 1] : 0.f) : whi[c][s];
                float prev = __shfl_sync(0xffffffffu, pubp, (lane + 31) & 31);
                // next = elem(d1+1): lane l+1's lo[s]; lane31 <- lane0's lo[s+1] (0 if s==2)
                float pubn = (lane == 0) ? (s < 2 ? wlo[c][s + 1] : 0.f) : wlo[c][s];
                float next = __shfl_sync(0xffffffffu, pubn, (lane + 1) & 31);
                float tt = wlo[c][s] + whi[c][s];
                o[c][s] = add2(pk2(tt, tt), pk2(prev, next));
            }
        }
        #pragma unroll
        for (int s = 0; s < 3; s++) {
            u64 sI = o[0][s], sJ = o[1][s];
            u64 m1n = mul2(sI, ninv2);
            u64 m2n = mul2(sJ, ninv2);
            u64 cross = fma2(m2n, sI, o[4][s]);   // sum((I-uI)(J-uJ))
            u64 Iv    = fma2(m1n, sI, o[2][s]);   // sum((I-uI)^2)
            u64 Jv    = fma2(m2n, sJ, o[3][s]);   // sum((J-uJ)^2)
            u64 den   = fma2(Iv, Jv, eps2);
            u64 num   = mul2(cross, cross);
            float n0, n1, d0, d1;
            upk2(num, n0, n1);
            upk2(den, d0, d1);
            acc += __fdividef(n0, d0) + __fdividef(n1, d1);
        }
        #pragma unroll
        for (int r = 0; r < 3; r++) { pI[r] += SZ; pJ[r] += SZ; }
    }

    // ---- deterministic in-kernel reduction ----
    __shared__ float  sred[64];
    __shared__ double dred[64];
    __shared__ unsigned int s_last;
    const int tid = threadIdx.y * 32 + lane;

    sred[tid] = acc;
    __syncthreads();
    #pragma unroll
    for (int s = 32; s > 0; s >>= 1) {
        if (tid < s) sred[tid] += sred[tid + s];
        __syncthreads();
    }
    if (tid == 0) {
        const int blin = blockIdx.y + GY * blockIdx.z;
        g_partial[blin] = sred[0];
        __threadfence();
        unsigned old = atomicAdd(&g_count, 1u);
        s_last = (old == (unsigned)(NBLK - 1)) ? 1u : 0u;
    }
    __syncthreads();

    if (s_last) {
        double v = 0.0;
        for (int i = tid; i < NBLK; i += 64)
            v += (double)g_partial[i];
        dred[tid] = v;
        __syncthreads();
        #pragma unroll
        for (int k = 32; k > 0; k >>= 1) {
            if (tid < k) dred[tid] += dred[tid + k];
            __syncthreads();
        }
        if (tid == 0) {
            out[0] = (float)(-dred[0] / (double)NTOT);
            g_count = 0;   // reset for the next (graph-replayed) call
        }
    }
}

extern "C" void kernel_launch(void* const* d_in, const int* in_sizes, int n_in,
                              void* d_out, int out_size) {
    const float* pred = (const float*)d_in[0];
    const float* targ = (const float*)d_in[1];
    dim3 grid(1, GY, GZ);
    dim3 block(32, 2, 1);
    lncc_fused_kernel<<<grid, block>>>(pred, targ, (float*)d_out);
}

// round 11
// speedup vs baseline: 1.2087x; 1.2087x over previous
#include <cuda_runtime.h>

// Fused local NCC loss (kernel=3, zero 'same' padding) over 192^3 f32 volumes.
// One warp spans the full d=192: lane owns d={2l, 64+2l, 128+2l} as f32x2
// packs (coalesced LDG.64). H=1 row per warp; rows h-1,h,h+1 via per-row
// pointers (zero-buffer redirect at h edges). w marched with a 2-plane
// T-scheme ring built in place; all 18 plane loads batched per build.
// d-window seams via publish-SEL + index-shfl; packed f32x2 NCC epilogue.
// NEW: register-neutral prefetch.global.L1 of the next iteration's planes
// (lane-strided to cover the full 768B row span) to hide L2 latency.

#define SZ    192
#define SZ2   (SZ * SZ)
#define NTOT  (SZ * SZ * SZ)
#define WCHUNK 16
#define GY     96              // 192 h rows / 2 warps per block
#define GZ     12              // 192 / WCHUNK
#define NBLK   (GY * GZ)       // 1152  (~one full wave at 8 blocks/SM)

typedef unsigned long long u64;

__device__ float        g_zero[4608];          // static zero (BSS) pad source
__device__ float        g_partial[NBLK];
__device__ unsigned int g_count = 0;

__device__ __forceinline__ u64 pk2(float lo, float hi) {
    u64 r; asm("mov.b64 %0, {%1, %2};" : "=l"(r) : "f"(lo), "f"(hi)); return r;
}
__device__ __forceinline__ void upk2(u64 v, float& lo, float& hi) {
    asm("mov.b64 {%0, %1}, %2;" : "=f"(lo), "=f"(hi) : "l"(v));
}
__device__ __forceinline__ u64 add2(u64 a, u64 b) {
    u64 r; asm("add.rn.f32x2 %0, %1, %2;" : "=l"(r) : "l"(a), "l"(b)); return r;
}
__device__ __forceinline__ u64 mul2(u64 a, u64 b) {
    u64 r; asm("mul.rn.f32x2 %0, %1, %2;" : "=l"(r) : "l"(a), "l"(b)); return r;
}
__device__ __forceinline__ u64 fma2(u64 a, u64 b, u64 c) {
    u64 r; asm("fma.rn.f32x2 %0, %1, %2, %3;" : "=l"(r) : "l"(a), "l"(b), "l"(c)); return r;
}
__device__ __forceinline__ void pf_l1(const float* p) {
    asm volatile("prefetch.global.L1 [%0];" :: "l"(p));
}

struct PS { u64 v[5][3]; };   // components {I,J,II,JJ,IJ} x packs {s=0,1,2}

// Build plane sums over the 3 h-rows. foff = float offset of this plane
// relative to the (already w-positioned) row pointers.
__device__ __forceinline__ void build_plane(
    PS& C, const float* const (&pI)[3], const float* const (&pJ)[3],
    int foff, int wp)
{
    if ((unsigned)wp >= (unsigned)SZ) {
        #pragma unroll
        for (int c = 0; c < 5; c++)
            #pragma unroll
            for (int s = 0; s < 3; s++) C.v[c][s] = 0ull;
        return;
    }
    #pragma unroll
    for (int s = 0; s < 3; s++) {
        u64 aI, aJ, aII, aJJ, aIJ;
        #pragma unroll
        for (int r = 0; r < 3; r++) {
            u64 I = *(const u64*)(pI[r] + foff + 64 * s);
            u64 J = *(const u64*)(pJ[r] + foff + 64 * s);
            if (r == 0) {
                aI = I; aJ = J;
                aII = mul2(I, I); aJJ = mul2(J, J); aIJ = mul2(I, J);
            } else {
                aI = add2(aI, I); aJ = add2(aJ, J);
                aII = fma2(I, I, aII); aJJ = fma2(J, J, aJJ); aIJ = fma2(I, J, aIJ);
            }
        }
        C.v[0][s] = aI; C.v[1][s] = aJ; C.v[2][s] = aII; C.v[3][s] = aJJ; C.v[4][s] = aIJ;
    }
}

// Emit one output w-plane: window sums = T + Cr; also updates T = Bo + Cr.
__device__ __forceinline__ float emit(PS& T, const PS& Bo, const PS& Cr,
                                      int lane, u64 ninv2, u64 eps2)
{
    u64 o[5][3];   // per component: packed (out[2s], out[2s+1])
    #pragma unroll
    for (int c = 0; c < 5; c++) {
        float lo[3], hi[3];
        #pragma unroll
        for (int s = 0; s < 3; s++) {
            u64 Pw = add2(T.v[c][s], Cr.v[c][s]);
            T.v[c][s] = add2(Bo.v[c][s], Cr.v[c][s]);
            upk2(Pw, lo[s], hi[s]);
        }
        #pragma unroll
        for (int s = 0; s < 3; s++) {
            // prev = elem(d0-1): lane l-1's hi[s]; lane0 <- lane31's hi[s-1] (0 if s==0)
            float pubp = (lane == 31) ? (s ? hi[s - 1] : 0.f) : hi[s];
            float prev = __shfl_sync(0xffffffffu, pubp, (lane + 31) & 31);
            // next = elem(d1+1): lane l+1's lo[s]; lane31 <- lane0's lo[s+1] (0 if s==2)
            float pubn = (lane == 0) ? (s < 2 ? lo[s + 1] : 0.f) : lo[s];
            float next = __shfl_sync(0xffffffffu, pubn, (lane + 1) & 31);
            float t = lo[s] + hi[s];
            o[c][s] = add2(pk2(t, t), pk2(prev, next));
        }
    }
    float acc = 0.f;
    #pragma unroll
    for (int s = 0; s < 3; s++) {
        u64 sI = o[0][s], sJ = o[1][s];
        u64 m1n = mul2(sI, ninv2);
        u64 m2n = mul2(sJ, ninv2);
        u64 cross = fma2(m2n, sI, o[4][s]);   // sum((I-uI)(J-uJ))
        u64 Iv    = fma2(m1n, sI, o[2][s]);   // sum((I-uI)^2)
        u64 Jv    = fma2(m2n, sJ, o[3][s]);   // sum((J-uJ)^2)
        u64 den   = fma2(Iv, Jv, eps2);
        u64 num   = mul2(cross, cross);
        float n0, n1, d0, d1;
        upk2(num, n0, n1);
        upk2(den, d0, d1);
        acc += __fdividef(n0, d0) + __fdividef(n1, d1);
    }
    return acc;
}

__global__ __launch_bounds__(64, 8)
void lncc_fused_kernel(const float* __restrict__ pred,
                       const float* __restrict__ targ,
                       float* __restrict__ out)
{
    const int lane = threadIdx.x;                  // 0..31
    const int h    = blockIdx.y * 2 + threadIdx.y; // one h row per warp
    const int w0   = blockIdx.z * WCHUNK;

    const u64 ninv2 = pk2(-1.0f / 27.0f, -1.0f / 27.0f);
    const u64 eps2  = pk2(1e-5f, 1e-5f);

    // Per-row pointers (w-positioned at plane w0-1, lane-offset applied);
    // out-of-range h rows redirect into the static zero buffer.
    const float* pI[3];
    const float* pJ[3];
    #pragma unroll
    for (int r = 0; r < 3; r++) {
        int hh = h - 1 + r;
        bool ok = (hh >= 0) && (hh < SZ);
        long off = (long)hh * SZ2 + (long)(w0 - 1) * SZ + 2 * lane;
        pI[r] = ok ? pred + off : g_zero + 2 * lane;
        pJ[r] = ok ? targ + off : g_zero + 2 * lane;
    }
    // lane-strided prefetch offset: 32 lanes x 24 floats = 768B = full row span
    const int pfoff = 22 * lane;   // pointers already carry +2*lane

    PS T, B0, B1;
    int wp = w0 - 1;
    build_plane(B0, pI, pJ, 0,  wp);        // plane k=0
    build_plane(B1, pI, pJ, SZ, wp + 1);    // plane k=1
    #pragma unroll
    for (int c = 0; c < 5; c++)
        #pragma unroll
        for (int s = 0; s < 3; s++)
            T.v[c][s] = add2(B0.v[c][s], B1.v[c][s]);
    #pragma unroll
    for (int r = 0; r < 3; r++) { pI[r] += 2 * SZ; pJ[r] += 2 * SZ; }
    wp += 2;

    float acc = 0.f;
    // planes k=2..17 (16 emits), C alternates into B0/B1 (in-place ring)
    for (int t = 0; t < WCHUNK / 2; t++) {
        build_plane(B0, pI, pJ, 0, wp);        // even plane: Cr=B0, Bo=B1
        // prefetch next iteration's two planes (wp+2, wp+3) into L1
        if (wp + 2 < SZ) {
            #pragma unroll
            for (int r = 0; r < 3; r++) {
                pf_l1(pI[r] + 2 * SZ + pfoff);
                pf_l1(pJ[r] + 2 * SZ + pfoff);
            }
        }
        if (wp + 3 < SZ) {
            #pragma unroll
            for (int r = 0; r < 3; r++) {
                pf_l1(pI[r] + 3 * SZ + pfoff);
                pf_l1(pJ[r] + 3 * SZ + pfoff);
            }
        }
        acc += emit(T, B1, B0, lane, ninv2, eps2);
        build_plane(B1, pI, pJ, SZ, wp + 1);   // odd plane:  Cr=B1, Bo=B0
        acc += emit(T, B0, B1, lane, ninv2, eps2);
        #pragma unroll
        for (int r = 0; r < 3; r++) { pI[r] += 2 * SZ; pJ[r] += 2 * SZ; }
        wp += 2;
    }

    // ---- deterministic in-kernel reduction ----
    __shared__ float  sred[64];
    __shared__ double dred[64];
    __shared__ unsigned int s_last;
    const int tid = threadIdx.y * 32 + lane;

    sred[tid] = acc;
    __syncthreads();
    #pragma unroll
    for (int s = 32; s > 0; s >>= 1) {
        if (tid < s) sred[tid] += sred[tid + s];
        __syncthreads();
    }
    if (tid == 0) {
        const int blin = blockIdx.y + GY * blockIdx.z;
        g_partial[blin] = sred[0];
        __threadfence();
        unsigned old = atomicAdd(&g_count, 1u);
        s_last = (old == (unsigned)(NBLK - 1)) ? 1u : 0u;
    }
    __syncthreads();

    if (s_last) {
        double v = 0.0;
        for (int i = tid; i < NBLK; i += 64)
            v += (double)g_partial[i];
        dred[tid] = v;
        __syncthreads();
        #pragma unroll
        for (int k = 32; k > 0; k >>= 1) {
            if (tid < k) dred[tid] += dred[tid + k];
            __syncthreads();
        }
        if (tid == 0) {
            out[0] = (float)(-dred[0] / (double)NTOT);
            g_count = 0;   // reset for the next (graph-replayed) call
        }
    }
}

extern "C" void kernel_launch(void* const* d_in, const int* in_sizes, int n_in,
                              void* d_out, int out_size) {
    const float* pred = (const float*)d_in[0];
    const float* targ = (const float*)d_in[1];
    dim3 grid(1, GY, GZ);
    dim3 block(32, 2, 1);
    lncc_fused_kernel<<<grid, block>>>(pred, targ, (float*)d_out);
}

// round 12
// speedup vs baseline: 1.9223x; 1.5905x over previous
#include <cuda_runtime.h>

// Fused local NCC loss (kernel=3, zero 'same' padding) over 192^3 f32 volumes.
// One warp spans the full d=192: lane owns d={2l, 64+2l, 128+2l} as f32x2
// packs (coalesced LDG.64). H=1 row per warp; rows h-1,h,h+1 via per-row
// pointers (zero-buffer redirect at h edges). w marched with a 2-plane
// T-scheme ring built in place; all 18 plane loads batched per build.
// d-window seams via publish-SEL + index-shfl; packed f32x2 NCC epilogue
// with the two divides per pack fused into one (halved MUFU pressure).

#define SZ    192
#define SZ2   (SZ * SZ)
#define NTOT  (SZ * SZ * SZ)
#define WCHUNK 16
#define GY     96              // 192 h rows / 2 warps per block
#define GZ     12              // 192 / WCHUNK
#define NBLK   (GY * GZ)       // 1152  (~one full wave at 8 blocks/SM)

typedef unsigned long long u64;

__device__ float        g_zero[4608];          // static zero (BSS) pad source
__device__ float        g_partial[NBLK];
__device__ unsigned int g_count = 0;

__device__ __forceinline__ u64 pk2(float lo, float hi) {
    u64 r; asm("mov.b64 %0, {%1, %2};" : "=l"(r) : "f"(lo), "f"(hi)); return r;
}
__device__ __forceinline__ void upk2(u64 v, float& lo, float& hi) {
    asm("mov.b64 {%0, %1}, %2;" : "=f"(lo), "=f"(hi) : "l"(v));
}
__device__ __forceinline__ u64 add2(u64 a, u64 b) {
    u64 r; asm("add.rn.f32x2 %0, %1, %2;" : "=l"(r) : "l"(a), "l"(b)); return r;
}
__device__ __forceinline__ u64 mul2(u64 a, u64 b) {
    u64 r; asm("mul.rn.f32x2 %0, %1, %2;" : "=l"(r) : "l"(a), "l"(b)); return r;
}
__device__ __forceinline__ u64 fma2(u64 a, u64 b, u64 c) {
    u64 r; asm("fma.rn.f32x2 %0, %1, %2, %3;" : "=l"(r) : "l"(a), "l"(b), "l"(c)); return r;
}

struct PS { u64 v[5][3]; };   // components {I,J,II,JJ,IJ} x packs {s=0,1,2}

// Build plane sums over the 3 h-rows. foff = float offset of this plane
// relative to the (already w-positioned) row pointers.
__device__ __forceinline__ void build_plane(
    PS& C, const float* const (&pI)[3], const float* const (&pJ)[3],
    int foff, int wp)
{
    if ((unsigned)wp >= (unsigned)SZ) {
        #pragma unroll
        for (int c = 0; c < 5; c++)
            #pragma unroll
            for (int s = 0; s < 3; s++) C.v[c][s] = 0ull;
        return;
    }
    #pragma unroll
    for (int s = 0; s < 3; s++) {
        u64 aI, aJ, aII, aJJ, aIJ;
        #pragma unroll
        for (int r = 0; r < 3; r++) {
            u64 I = *(const u64*)(pI[r] + foff + 64 * s);
            u64 J = *(const u64*)(pJ[r] + foff + 64 * s);
            if (r == 0) {
                aI = I; aJ = J;
                aII = mul2(I, I); aJJ = mul2(J, J); aIJ = mul2(I, J);
            } else {
                aI = add2(aI, I); aJ = add2(aJ, J);
                aII = fma2(I, I, aII); aJJ = fma2(J, J, aJJ); aIJ = fma2(I, J, aIJ);
            }
        }
        C.v[0][s] = aI; C.v[1][s] = aJ; C.v[2][s] = aII; C.v[3][s] = aJJ; C.v[4][s] = aIJ;
    }
}

// Emit one output w-plane: window sums = T + Cr; also updates T = Bo + Cr.
__device__ __forceinline__ float emit(PS& T, const PS& Bo, const PS& Cr,
                                      int lane, u64 ninv2, u64 eps2)
{
    u64 o[5][3];   // per component: packed (out[2s], out[2s+1])
    #pragma unroll
    for (int c = 0; c < 5; c++) {
        float lo[3], hi[3];
        #pragma unroll
        for (int s = 0; s < 3; s++) {
            u64 Pw = add2(T.v[c][s], Cr.v[c][s]);
            T.v[c][s] = add2(Bo.v[c][s], Cr.v[c][s]);
            upk2(Pw, lo[s], hi[s]);
        }
        #pragma unroll
        for (int s = 0; s < 3; s++) {
            // prev = elem(d0-1): lane l-1's hi[s]; lane0 <- lane31's hi[s-1] (0 if s==0)
            float pubp = (lane == 31) ? (s ? hi[s - 1] : 0.f) : hi[s];
            float prev = __shfl_sync(0xffffffffu, pubp, (lane + 31) & 31);
            // next = elem(d1+1): lane l+1's lo[s]; lane31 <- lane0's lo[s+1] (0 if s==2)
            float pubn = (lane == 0) ? (s < 2 ? lo[s + 1] : 0.f) : lo[s];
            float next = __shfl_sync(0xffffffffu, pubn, (lane + 1) & 31);
            float t = lo[s] + hi[s];
            o[c][s] = add2(pk2(t, t), pk2(prev, next));
        }
    }
    float acc = 0.f;
    #pragma unroll
    for (int s = 0; s < 3; s++) {
        u64 sI = o[0][s], sJ = o[1][s];
        u64 m1n = mul2(sI, ninv2);
        u64 m2n = mul2(sJ, ninv2);
        u64 cross = fma2(m2n, sI, o[4][s]);   // sum((I-uI)(J-uJ))
        u64 Iv    = fma2(m1n, sI, o[2][s]);   // sum((I-uI)^2)
        u64 Jv    = fma2(m2n, sJ, o[3][s]);   // sum((J-uJ)^2)
        u64 den   = fma2(Iv, Jv, eps2);
        u64 num   = mul2(cross, cross);
        float n0, n1, d0, d1;
        upk2(num, n0, n1);
        upk2(den, d0, d1);
        // n0/d0 + n1/d1 = (n0*d1 + n1*d0) / (d0*d1): one divide per pack
        float top = fmaf(n0, d1, n1 * d0);
        acc += __fdividef(top, d0 * d1);
    }
    return acc;
}

__global__ __launch_bounds__(64, 8)
void lncc_fused_kernel(const float* __restrict__ pred,
                       const float* __restrict__ targ,
                       float* __restrict__ out)
{
    const int lane = threadIdx.x;                  // 0..31
    const int h    = blockIdx.y * 2 + threadIdx.y; // one h row per warp
    const int w0   = blockIdx.z * WCHUNK;

    const u64 ninv2 = pk2(-1.0f / 27.0f, -1.0f / 27.0f);
    const u64 eps2  = pk2(1e-5f, 1e-5f);

    // Per-row pointers (w-positioned at plane w0-1, lane-offset applied);
    // out-of-range h rows redirect into the static zero buffer.
    const float* pI[3];
    const float* pJ[3];
    #pragma unroll
    for (int r = 0; r < 3; r++) {
        int hh = h - 1 + r;
        bool ok = (hh >= 0) && (hh < SZ);
        long off = (long)hh * SZ2 + (long)(w0 - 1) * SZ + 2 * lane;
        pI[r] = ok ? pred + off : g_zero + 2 * lane;
        pJ[r] = ok ? targ + off : g_zero + 2 * lane;
    }

    PS T, B0, B1;
    int wp = w0 - 1;
    build_plane(B0, pI, pJ, 0,  wp);        // plane k=0
    build_plane(B1, pI, pJ, SZ, wp + 1);    // plane k=1
    #pragma unroll
    for (int c = 0; c < 5; c++)
        #pragma unroll
        for (int s = 0; s < 3; s++)
            T.v[c][s] = add2(B0.v[c][s], B1.v[c][s]);
    #pragma unroll
    for (int r = 0; r < 3; r++) { pI[r] += 2 * SZ; pJ[r] += 2 * SZ; }
    wp += 2;

    float acc = 0.f;
    // planes k=2..17 (16 emits), C alternates into B0/B1 (in-place ring)
    #pragma unroll 2
    for (int t = 0; t < WCHUNK / 2; t++) {
        build_plane(B0, pI, pJ, 0, wp);        // even plane: Cr=B0, Bo=B1
        acc += emit(T, B1, B0, lane, ninv2, eps2);
        build_plane(B1, pI, pJ, SZ, wp + 1);   // odd plane:  Cr=B1, Bo=B0
        acc += emit(T, B0, B1, lane, ninv2, eps2);
        #pragma unroll
        for (int r = 0; r < 3; r++) { pI[r] += 2 * SZ; pJ[r] += 2 * SZ; }
        wp += 2;
    }

    // ---- deterministic in-kernel reduction ----
    __shared__ float  sred[64];
    __shared__ double dred[64];
    __shared__ unsigned int s_last;
    const int tid = threadIdx.y * 32 + lane;

    sred[tid] = acc;
    __syncthreads();
    #pragma unroll
    for (int s = 32; s > 0; s >>= 1) {
        if (tid < s) sred[tid] += sred[tid + s];
        __syncthreads();
    }
    if (tid == 0) {
        const int blin = blockIdx.y + GY * blockIdx.z;
        g_partial[blin] = sred[0];
        __threadfence();
        unsigned old = atomicAdd(&g_count, 1u);
        s_last = (old == (unsigned)(NBLK - 1)) ? 1u : 0u;
    }
    __syncthreads();

    if (s_last) {
        double v = 0.0;
        for (int i = tid; i < NBLK; i += 64)
            v += (double)g_partial[i];
        dred[tid] = v;
        __syncthreads();
        #pragma unroll
        for (int k = 32; k > 0; k >>= 1) {
            if (tid < k) dred[tid] += dred[tid + k];
            __syncthreads();
        }
        if (tid == 0) {
            out[0] = (float)(-dred[0] / (double)NTOT);
            g_count = 0;   // reset for the next (graph-replayed) call
        }
    }
}

extern "C" void kernel_launch(void* const* d_in, const int* in_sizes, int n_in,
                              void* d_out, int out_size) {
    const float* pred = (const float*)d_in[0];
    const float* targ = (const float*)d_in[1];
    dim3 grid(1, GY, GZ);
    dim3 block(32, 2, 1);
    lncc_fused_kernel<<<grid, block>>>(pred, targ, (float*)d_out);
}

// round 13
// speedup vs baseline: 2.2523x; 1.1717x over previous
#include <cuda_runtime.h>

// Fused local NCC loss (kernel=3, zero 'same' padding) over 192^3 f32 volumes.
// One warp spans the full d=192: lane owns d={2l, 64+2l, 128+2l} as f32x2
// packs (coalesced LDG.64). H=1 row per warp; rows h-1,h,h+1 via per-row
// pointers (zero-buffer redirect at h edges). w marched with a 2-plane
// T-scheme ring built in place; all 18 plane loads batched per build.
// d-window seams via publish-SEL + index-shfl; packed f32x2 NCC epilogue.
// 4 warps per block over adjacent h rows: interior halo rows are the sibling
// warps' center rows -> L1-warm (row redundancy 2.0x -> 1.5x per block).

#define SZ    192
#define SZ2   (SZ * SZ)
#define NTOT  (SZ * SZ * SZ)
#define WCHUNK 16
#define BY     4               // warps (h rows) per block
#define GY     48              // 192 / BY
#define GZ     12              // 192 / WCHUNK
#define NBLK   (GY * GZ)       // 576 (one wave at 4 blocks/SM)

typedef unsigned long long u64;

__device__ float        g_zero[4608];          // static zero (BSS) pad source
__device__ float        g_partial[NBLK];
__device__ unsigned int g_count = 0;

__device__ __forceinline__ u64 pk2(float lo, float hi) {
    u64 r; asm("mov.b64 %0, {%1, %2};" : "=l"(r) : "f"(lo), "f"(hi)); return r;
}
__device__ __forceinline__ void upk2(u64 v, float& lo, float& hi) {
    asm("mov.b64 {%0, %1}, %2;" : "=f"(lo), "=f"(hi) : "l"(v));
}
__device__ __forceinline__ u64 add2(u64 a, u64 b) {
    u64 r; asm("add.rn.f32x2 %0, %1, %2;" : "=l"(r) : "l"(a), "l"(b)); return r;
}
__device__ __forceinline__ u64 mul2(u64 a, u64 b) {
    u64 r; asm("mul.rn.f32x2 %0, %1, %2;" : "=l"(r) : "l"(a), "l"(b)); return r;
}
__device__ __forceinline__ u64 fma2(u64 a, u64 b, u64 c) {
    u64 r; asm("fma.rn.f32x2 %0, %1, %2, %3;" : "=l"(r) : "l"(a), "l"(b), "l"(c)); return r;
}

struct PS { u64 v[5][3]; };   // components {I,J,II,JJ,IJ} x packs {s=0,1,2}

// Build plane sums over the 3 h-rows. foff = float offset of this plane
// relative to the (already w-positioned) row pointers.
__device__ __forceinline__ void build_plane(
    PS& C, const float* const (&pI)[3], const float* const (&pJ)[3],
    int foff, int wp)
{
    if ((unsigned)wp >= (unsigned)SZ) {
        #pragma unroll
        for (int c = 0; c < 5; c++)
            #pragma unroll
            for (int s = 0; s < 3; s++) C.v[c][s] = 0ull;
        return;
    }
    #pragma unroll
    for (int s = 0; s < 3; s++) {
        u64 aI, aJ, aII, aJJ, aIJ;
        #pragma unroll
        for (int r = 0; r < 3; r++) {
            u64 I = *(const u64*)(pI[r] + foff + 64 * s);
            u64 J = *(const u64*)(pJ[r] + foff + 64 * s);
            if (r == 0) {
                aI = I; aJ = J;
                aII = mul2(I, I); aJJ = mul2(J, J); aIJ = mul2(I, J);
            } else {
                aI = add2(aI, I); aJ = add2(aJ, J);
                aII = fma2(I, I, aII); aJJ = fma2(J, J, aJJ); aIJ = fma2(I, J, aIJ);
            }
        }
        C.v[0][s] = aI; C.v[1][s] = aJ; C.v[2][s] = aII; C.v[3][s] = aJJ; C.v[4][s] = aIJ;
    }
}

// Emit one output w-plane: window sums = T + Cr; also updates T = Bo + Cr.
__device__ __forceinline__ float emit(PS& T, const PS& Bo, const PS& Cr,
                                      int lane, u64 ninv2, u64 eps2)
{
    u64 o[5][3];   // per component: packed (out[2s], out[2s+1])
    #pragma unroll
    for (int c = 0; c < 5; c++) {
        float lo[3], hi[3];
        #pragma unroll
        for (int s = 0; s < 3; s++) {
            u64 Pw = add2(T.v[c][s], Cr.v[c][s]);
            T.v[c][s] = add2(Bo.v[c][s], Cr.v[c][s]);
            upk2(Pw, lo[s], hi[s]);
        }
        #pragma unroll
        for (int s = 0; s < 3; s++) {
            // prev = elem(d0-1): lane l-1's hi[s]; lane0 <- lane31's hi[s-1] (0 if s==0)
            float pubp = (lane == 31) ? (s ? hi[s - 1] : 0.f) : hi[s];
            float prev = __shfl_sync(0xffffffffu, pubp, (lane + 31) & 31);
            // next = elem(d1+1): lane l+1's lo[s]; lane31 <- lane0's lo[s+1] (0 if s==2)
            float pubn = (lane == 0) ? (s < 2 ? lo[s + 1] : 0.f) : lo[s];
            float next = __shfl_sync(0xffffffffu, pubn, (lane + 1) & 31);
            float t = lo[s] + hi[s];
            o[c][s] = add2(pk2(t, t), pk2(prev, next));
        }
    }
    float acc = 0.f;
    #pragma unroll
    for (int s = 0; s < 3; s++) {
        u64 sI = o[0][s], sJ = o[1][s];
        u64 m1n = mul2(sI, ninv2);
        u64 m2n = mul2(sJ, ninv2);
        u64 cross = fma2(m2n, sI, o[4][s]);   // sum((I-uI)(J-uJ))
        u64 Iv    = fma2(m1n, sI, o[2][s]);   // sum((I-uI)^2)
        u64 Jv    = fma2(m2n, sJ, o[3][s]);   // sum((J-uJ)^2)
        u64 den   = fma2(Iv, Jv, eps2);
        u64 num   = mul2(cross, cross);
        float n0, n1, d0, d1;
        upk2(num, n0, n1);
        upk2(den, d0, d1);
        acc += __fdividef(n0, d0) + __fdividef(n1, d1);
    }
    return acc;
}

__global__ __launch_bounds__(32 * BY, 4)
void lncc_fused_kernel(const float* __restrict__ pred,
                       const float* __restrict__ targ,
                       float* __restrict__ out)
{
    const int lane = threadIdx.x;                   // 0..31
    const int h    = blockIdx.y * BY + threadIdx.y; // one h row per warp
    const int w0   = blockIdx.z * WCHUNK;

    const u64 ninv2 = pk2(-1.0f / 27.0f, -1.0f / 27.0f);
    const u64 eps2  = pk2(1e-5f, 1e-5f);

    // Per-row pointers (w-positioned at plane w0-1, lane-offset applied);
    // out-of-range h rows redirect into the static zero buffer.
    const float* pI[3];
    const float* pJ[3];
    #pragma unroll
    for (int r = 0; r < 3; r++) {
        int hh = h - 1 + r;
        bool ok = (hh >= 0) && (hh < SZ);
        long off = (long)hh * SZ2 + (long)(w0 - 1) * SZ + 2 * lane;
        pI[r] = ok ? pred + off : g_zero + 2 * lane;
        pJ[r] = ok ? targ + off : g_zero + 2 * lane;
    }

    PS T, B0, B1;
    int wp = w0 - 1;
    build_plane(B0, pI, pJ, 0,  wp);        // plane k=0
    build_plane(B1, pI, pJ, SZ, wp + 1);    // plane k=1
    #pragma unroll
    for (int c = 0; c < 5; c++)
        #pragma unroll
        for (int s = 0; s < 3; s++)
            T.v[c][s] = add2(B0.v[c][s], B1.v[c][s]);
    #pragma unroll
    for (int r = 0; r < 3; r++) { pI[r] += 2 * SZ; pJ[r] += 2 * SZ; }
    wp += 2;

    float acc = 0.f;
    // planes k=2..17 (16 emits), C alternates into B0/B1 (in-place ring)
    for (int t = 0; t < WCHUNK / 2; t++) {
        build_plane(B0, pI, pJ, 0, wp);        // even plane: Cr=B0, Bo=B1
        acc += emit(T, B1, B0, lane, ninv2, eps2);
        build_plane(B1, pI, pJ, SZ, wp + 1);   // odd plane:  Cr=B1, Bo=B0
        acc += emit(T, B0, B1, lane, ninv2, eps2);
        #pragma unroll
        for (int r = 0; r < 3; r++) { pI[r] += 2 * SZ; pJ[r] += 2 * SZ; }
        wp += 2;
    }

    // ---- deterministic in-kernel reduction ----
    __shared__ float  sred[32 * BY];
    __shared__ double dred[32 * BY];
    __shared__ unsigned int s_last;
    const int tid = threadIdx.y * 32 + lane;

    sred[tid] = acc;
    __syncthreads();
    #pragma unroll
    for (int s = 16 * BY; s > 0; s >>= 1) {
        if (tid < s) sred[tid] += sred[tid + s];
        __syncthreads();
    }
    if (tid == 0) {
        const int blin = blockIdx.y + GY * blockIdx.z;
        g_partial[blin] = sred[0];
        __threadfence();
        unsigned old = atomicAdd(&g_count, 1u);
        s_last = (old == (unsigned)(NBLK - 1)) ? 1u : 0u;
    }
    __syncthreads();

    if (s_last) {
        double v = 0.0;
        for (int i = tid; i < NBLK; i += 32 * BY)
            v += (double)g_partial[i];
        dred[tid] = v;
        __syncthreads();
        #pragma unroll
        for (int k = 16 * BY; k > 0; k >>= 1) {
            if (tid < k) dred[tid] += dred[tid + k];
            __syncthreads();
        }
        if (tid == 0) {
            out[0] = (float)(-dred[0] / (double)NTOT);
            g_count = 0;   // reset for the next (graph-replayed) call
        }
    }
}

extern "C" void kernel_launch(void* const* d_in, const int* in_sizes, int n_in,
                              void* d_out, int out_size) {
    const float* pred = (const float*)d_in[0];
    const float* targ = (const float*)d_in[1];
    dim3 grid(1, GY, GZ);
    dim3 block(32, BY, 1);
    lncc_fused_kernel<<<grid, block>>>(pred, targ, (float*)d_out);
}